// round 4
// baseline (speedup 1.0000x reference)
#include <cuda_runtime.h>
#include <math.h>

// Problem constants
#define BB   8
#define SS   1024
#define HH   512
#define NHH  8
#define HDD  64

// Scratch for q, k, v in [B, NH, S, HD] layout (16 MB each). __device__ globals
// are the allowed scratch mechanism (no cudaMalloc permitted).
__device__ float g_q[BB * NHH * SS * HDD];
__device__ float g_k[BB * NHH * SS * HDD];
__device__ float g_v[BB * NHH * SS * HDD];

// ---------------------------------------------------------------------------
// Kernel 1: QKV projection.  Y[m,n] = sum_k X[m,k] * W[n,k] + bias[n]
// M = B*S = 8192, N = 512, K = 512.  grid = (N/64, M/64, 3), block = 256.
// Output written directly in [B, NH, S, HD] layout; q scaled by 1/sqrt(HD).
// ---------------------------------------------------------------------------
__global__ __launch_bounds__(256) void qkv_kernel(
    const float* __restrict__ x,
    const float* __restrict__ Wq, const float* __restrict__ bq,
    const float* __restrict__ Wk, const float* __restrict__ bk,
    const float* __restrict__ Wv, const float* __restrict__ bv)
{
    __shared__ float As[64][17];   // As[m][kk]
    __shared__ float Bs[64][17];   // Bs[n][kk]

    const int z  = blockIdx.z;                 // 0=q, 1=k, 2=v
    const float* W    = (z == 0) ? Wq : (z == 1) ? Wk : Wv;
    const float* bias = (z == 0) ? bq : (z == 1) ? bk : bv;
    float*       out  = (z == 0) ? g_q : (z == 1) ? g_k : g_v;

    const int m0 = blockIdx.y * 64;
    const int n0 = blockIdx.x * 64;
    const int tid = threadIdx.x;
    const int tx = tid & 15;        // 0..15
    const int ty = tid >> 4;        // 0..15

    // cooperative load indices: each thread loads one float4 of A and one of B
    const int lm = tid >> 2;          // 0..63 (row within tile)
    const int lk = (tid & 3) * 4;     // 0,4,8,12 (k within BK)

    const float* xg = x + (size_t)(m0 + lm) * HH + lk;
    const float* wg = W + (size_t)(n0 + lm) * HH + lk;

    float acc[4][4];
#pragma unroll
    for (int i = 0; i < 4; i++)
#pragma unroll
        for (int j = 0; j < 4; j++) acc[i][j] = 0.0f;

    for (int k0 = 0; k0 < HH; k0 += 16) {
        float4 a4 = *reinterpret_cast<const float4*>(xg + k0);
        float4 b4 = *reinterpret_cast<const float4*>(wg + k0);
        __syncthreads();
        As[lm][lk + 0] = a4.x; As[lm][lk + 1] = a4.y;
        As[lm][lk + 2] = a4.z; As[lm][lk + 3] = a4.w;
        Bs[lm][lk + 0] = b4.x; Bs[lm][lk + 1] = b4.y;
        Bs[lm][lk + 2] = b4.z; Bs[lm][lk + 3] = b4.w;
        __syncthreads();

#pragma unroll
        for (int kk = 0; kk < 16; kk++) {
            float av[4], bv_[4];
#pragma unroll
            for (int i = 0; i < 4; i++) av[i]  = As[ty + 16 * i][kk];
#pragma unroll
            for (int j = 0; j < 4; j++) bv_[j] = Bs[tx + 16 * j][kk];
#pragma unroll
            for (int i = 0; i < 4; i++)
#pragma unroll
                for (int j = 0; j < 4; j++)
                    acc[i][j] = fmaf(av[i], bv_[j], acc[i][j]);
        }
    }

    // Epilogue: add bias, fold softmax scale into q, write to [B,NH,S,HD]
    const int head = n0 >> 6;           // n0 is a multiple of 64
    const float qscale = (z == 0) ? 0.125f : 1.0f;   // 1/sqrt(64)
    float bb[4];
#pragma unroll
    for (int j = 0; j < 4; j++) bb[j] = bias[n0 + tx + 16 * j];

#pragma unroll
    for (int i = 0; i < 4; i++) {
        const int m = m0 + ty + 16 * i;        // global row = b*S + s
        const int b = m >> 10;
        const int s = m & 1023;
        float* orow = out + (((size_t)(b * NHH + head)) * SS + s) * HDD;
#pragma unroll
        for (int j = 0; j < 4; j++) {
            orow[tx + 16 * j] = (acc[i][j] + bb[j]) * qscale;
        }
    }
}

// ---------------------------------------------------------------------------
// Kernel 2: flash attention per (b, h, 64-row q-tile).
// grid = (S/64, NH, B), block = 256 (16x16 logical), dynamic smem ~49.9 KB.
// Score tile 64x64 in registers (4x4 strided frags). P reuses the K buffer.
// ---------------------------------------------------------------------------
#define PITCH 65

__global__ __launch_bounds__(256, 2) void attn_kernel(
    const float* __restrict__ rel,    // [B, NH, S, S]
    const float* __restrict__ mask,   // [B, 1, 1, S]
    float* __restrict__ out)          // [B, S, H]
{
    extern __shared__ float sm[];
    float* q_s = sm;                    // [64][PITCH]
    float* k_s = sm + 64 * PITCH;       // [64][PITCH]  (reused as P)
    float* v_s = sm + 2 * 64 * PITCH;   // [64][PITCH]

    const int b  = blockIdx.z;
    const int h  = blockIdx.y;
    const int q0 = blockIdx.x * 64;
    const int bh = b * NHH + h;

    const int tid = threadIdx.x;
    const int tx = tid & 15;
    const int ty = tid >> 4;

    const float* qg = g_q + (size_t)bh * SS * HDD;
    const float* kg = g_k + (size_t)bh * SS * HDD;
    const float* vg = g_v + (size_t)bh * SS * HDD;

    // Load the q tile (64 x 64): 4 float4 per thread
    {
        const int dcol = (tid & 15) * 4;
#pragma unroll
        for (int u = 0; u < 4; u++) {
            const int row = (tid >> 4) + 16 * u;
            float4 t = *reinterpret_cast<const float4*>(
                qg + (size_t)(q0 + row) * HDD + dcol);
            q_s[row * PITCH + dcol + 0] = t.x;
            q_s[row * PITCH + dcol + 1] = t.y;
            q_s[row * PITCH + dcol + 2] = t.z;
            q_s[row * PITCH + dcol + 3] = t.w;
        }
    }

    float m_i[4], l_i[4], o[4][4];
#pragma unroll
    for (int i = 0; i < 4; i++) {
        m_i[i] = -1e30f;
        l_i[i] = 0.0f;
#pragma unroll
        for (int j = 0; j < 4; j++) o[i][j] = 0.0f;
    }

    for (int k0 = 0; k0 < SS; k0 += 64) {
        __syncthreads();   // protect k_s/v_s against previous iteration readers

        // Load K and V tiles (each 64 x 64)
        {
            const int dcol = (tid & 15) * 4;
#pragma unroll
            for (int u = 0; u < 4; u++) {
                const int row = (tid >> 4) + 16 * u;
                float4 kt = *reinterpret_cast<const float4*>(
                    kg + (size_t)(k0 + row) * HDD + dcol);
                float4 vt = *reinterpret_cast<const float4*>(
                    vg + (size_t)(k0 + row) * HDD + dcol);
                k_s[row * PITCH + dcol + 0] = kt.x;
                k_s[row * PITCH + dcol + 1] = kt.y;
                k_s[row * PITCH + dcol + 2] = kt.z;
                k_s[row * PITCH + dcol + 3] = kt.w;
                v_s[row * PITCH + dcol + 0] = vt.x;
                v_s[row * PITCH + dcol + 1] = vt.y;
                v_s[row * PITCH + dcol + 2] = vt.z;
                v_s[row * PITCH + dcol + 3] = vt.w;
            }
        }

        // Prefetch rel bias + mask for this tile (hides DRAM latency
        // under the score GEMM below)
        float msk[4];
#pragma unroll
        for (int j = 0; j < 4; j++)
            msk[j] = mask[b * SS + k0 + tx + 16 * j];
        float rl[4][4];
#pragma unroll
        for (int i = 0; i < 4; i++) {
            const size_t rbase = ((size_t)bh * SS + (q0 + ty + 16 * i)) * SS + k0;
#pragma unroll
            for (int j = 0; j < 4; j++)
                rl[i][j] = rel[rbase + tx + 16 * j];
        }

        __syncthreads();   // tiles visible

        // Scores: S = Q * K^T  (64x64x64), 4x4 frag per thread
        float s[4][4];
#pragma unroll
        for (int i = 0; i < 4; i++)
#pragma unroll
            for (int j = 0; j < 4; j++) s[i][j] = 0.0f;

#pragma unroll 4
        for (int d = 0; d < HDD; d++) {
            float qa[4], kb[4];
#pragma unroll
            for (int i = 0; i < 4; i++) qa[i] = q_s[(ty + 16 * i) * PITCH + d];
#pragma unroll
            for (int j = 0; j < 4; j++) kb[j] = k_s[(tx + 16 * j) * PITCH + d];
#pragma unroll
            for (int i = 0; i < 4; i++)
#pragma unroll
                for (int j = 0; j < 4; j++)
                    s[i][j] = fmaf(qa[i], kb[j], s[i][j]);
        }

#pragma unroll
        for (int i = 0; i < 4; i++)
#pragma unroll
            for (int j = 0; j < 4; j++)
                s[i][j] += rl[i][j] + msk[j];

        // Online softmax update (state replicated across the 16 tx lanes)
#pragma unroll
        for (int i = 0; i < 4; i++) {
            float tm = s[i][0];
#pragma unroll
            for (int j = 1; j < 4; j++) tm = fmaxf(tm, s[i][j]);
#pragma unroll
            for (int off = 8; off >= 1; off >>= 1)
                tm = fmaxf(tm, __shfl_xor_sync(0xffffffffu, tm, off));

            const float mn   = fmaxf(m_i[i], tm);
            const float corr = __expf(m_i[i] - mn);
            float ls = 0.0f;
#pragma unroll
            for (int j = 0; j < 4; j++) {
                s[i][j] = __expf(s[i][j] - mn);
                ls += s[i][j];
            }
#pragma unroll
            for (int off = 8; off >= 1; off >>= 1)
                ls += __shfl_xor_sync(0xffffffffu, ls, off);

            l_i[i] = l_i[i] * corr + ls;
            m_i[i] = mn;
#pragma unroll
            for (int j = 0; j < 4; j++) o[i][j] *= corr;
        }

        __syncthreads();   // everyone finished reading k_s as K

        // Write P into the K buffer
#pragma unroll
        for (int i = 0; i < 4; i++)
#pragma unroll
            for (int j = 0; j < 4; j++)
                k_s[(ty + 16 * i) * PITCH + tx + 16 * j] = s[i][j];

        __syncthreads();

        // O += P * V  (64x64x64)
#pragma unroll 4
        for (int kk = 0; kk < 64; kk++) {
            float pa[4], vb[4];
#pragma unroll
            for (int i = 0; i < 4; i++) pa[i] = k_s[(ty + 16 * i) * PITCH + kk];
#pragma unroll
            for (int j = 0; j < 4; j++) vb[j] = v_s[kk * PITCH + tx + 16 * j];
#pragma unroll
            for (int i = 0; i < 4; i++)
#pragma unroll
                for (int j = 0; j < 4; j++)
                    o[i][j] = fmaf(pa[i], vb[j], o[i][j]);
        }
    }

    // Epilogue: normalize by l, write ctx to [B, S, H] with head offset
#pragma unroll
    for (int i = 0; i < 4; i++) {
        const float inv = 1.0f / l_i[i];
        const int srow = q0 + ty + 16 * i;
        float* orow = out + ((size_t)(b * SS + srow)) * HH + h * HDD;
#pragma unroll
        for (int j = 0; j < 4; j++)
            orow[tx + 16 * j] = o[i][j] * inv;
    }
}

// ---------------------------------------------------------------------------
// Launch
// ---------------------------------------------------------------------------
extern "C" void kernel_launch(void* const* d_in, const int* in_sizes, int n_in,
                              void* d_out, int out_size)
{
    const float* hidden = (const float*)d_in[0];
    const float* mask   = (const float*)d_in[1];
    const float* rel    = (const float*)d_in[2];
    const float* Wq     = (const float*)d_in[3];
    const float* bq     = (const float*)d_in[4];
    const float* Wk     = (const float*)d_in[5];
    const float* bk     = (const float*)d_in[6];
    const float* Wv     = (const float*)d_in[7];
    const float* bv     = (const float*)d_in[8];
    float* out = (float*)d_out;

    const int smem_bytes = 3 * 64 * PITCH * (int)sizeof(float);  // 49,920 B
    cudaFuncSetAttribute(attn_kernel,
                         cudaFuncAttributeMaxDynamicSharedMemorySize,
                         smem_bytes);

    // QKV projection: grid (N/64, M/64, 3)
    qkv_kernel<<<dim3(HH / 64, (BB * SS) / 64, 3), 256>>>(
        hidden, Wq, bq, Wk, bk, Wv, bv);

    // Attention: grid (S/64, NH, B)
    attn_kernel<<<dim3(SS / 64, NHH, BB), 256, smem_bytes>>>(rel, mask, out);
}

// round 5
// speedup vs baseline: 3.0717x; 3.0717x over previous
#include <cuda_runtime.h>
#include <math.h>

// Problem constants
#define BB   8
#define SS   1024
#define HH   512
#define NHH  8
#define HDD  64

// Scratch for q, k, v in [B, NH, S, HD] layout (16 MB each).
__device__ float g_q[BB * NHH * SS * HDD];
__device__ float g_k[BB * NHH * SS * HDD];
__device__ float g_v[BB * NHH * SS * HDD];

// ---------------------------------------------------------------------------
// tf32 helpers
// ---------------------------------------------------------------------------
__device__ __forceinline__ unsigned f2tf(float x) {
    unsigned r;
    asm("cvt.rna.tf32.f32 %0, %1;" : "=r"(r) : "f"(x));
    return r;
}

// D(16x8,f32) += A(16x8,tf32,row) * B(8x8,tf32,col)
__device__ __forceinline__ void mma_tf32(float* d, const unsigned* a,
                                         const unsigned* b) {
    asm volatile(
        "mma.sync.aligned.m16n8k8.row.col.f32.tf32.tf32.f32 "
        "{%0,%1,%2,%3}, {%4,%5,%6,%7}, {%8,%9}, {%0,%1,%2,%3};"
        : "+f"(d[0]), "+f"(d[1]), "+f"(d[2]), "+f"(d[3])
        : "r"(a[0]), "r"(a[1]), "r"(a[2]), "r"(a[3]), "r"(b[0]), "r"(b[1]));
}

// ---------------------------------------------------------------------------
// Kernel 1: QKV projection with tf32 mma.
// Y[m,n] = sum_k X[m,k]*W[n,k] + bias[n].  M=8192, N=512, K=512.
// CTA tile 128x128, BK=32. 8 warps: warp tile 64(m) x 32(n).
// grid = (4, 64, 3), block = 256.
// ---------------------------------------------------------------------------
#define QP 36   // smem pitch (words) for BK=32 tiles

__global__ __launch_bounds__(256) void qkv_mma_kernel(
    const float* __restrict__ x,
    const float* __restrict__ Wq, const float* __restrict__ bq,
    const float* __restrict__ Wk, const float* __restrict__ bk,
    const float* __restrict__ Wv, const float* __restrict__ bv)
{
    __shared__ unsigned Xs[128][QP];
    __shared__ unsigned Ws[128][QP];

    const int z = blockIdx.z;
    const float* W    = (z == 0) ? Wq : (z == 1) ? Wk : Wv;
    const float* bias = (z == 0) ? bq : (z == 1) ? bk : bv;
    float*       out  = (z == 0) ? g_q : (z == 1) ? g_k : g_v;
    const float qscale = (z == 0) ? 0.125f : 1.0f;

    const int m0 = blockIdx.y * 128;
    const int n0 = blockIdx.x * 128;
    const int tid  = threadIdx.x;
    const int lane = tid & 31;
    const int wid  = tid >> 5;
    const int g    = lane >> 2;    // 0..7
    const int tig  = lane & 3;     // 0..3
    const int wm   = wid & 1;      // warp m (0..1) -> 64 rows
    const int wn   = wid >> 1;     // warp n (0..3) -> 32 cols

    const int lrow = tid >> 3;         // 0..31
    const int lcol = (tid & 7) * 4;    // 0,4,...,28

    float acc[4][4][4];
#pragma unroll
    for (int mt = 0; mt < 4; mt++)
#pragma unroll
        for (int nt = 0; nt < 4; nt++)
#pragma unroll
            for (int r = 0; r < 4; r++) acc[mt][nt][r] = 0.0f;

    for (int k0 = 0; k0 < HH; k0 += 32) {
        float4 xv[4], wv[4];
#pragma unroll
        for (int u = 0; u < 4; u++) {
            xv[u] = *reinterpret_cast<const float4*>(
                x + (size_t)(m0 + lrow + 32 * u) * HH + k0 + lcol);
            wv[u] = *reinterpret_cast<const float4*>(
                W + (size_t)(n0 + lrow + 32 * u) * HH + k0 + lcol);
        }
        __syncthreads();
#pragma unroll
        for (int u = 0; u < 4; u++) {
            unsigned* xd = &Xs[lrow + 32 * u][lcol];
            xd[0] = f2tf(xv[u].x); xd[1] = f2tf(xv[u].y);
            xd[2] = f2tf(xv[u].z); xd[3] = f2tf(xv[u].w);
            unsigned* wd = &Ws[lrow + 32 * u][lcol];
            wd[0] = f2tf(wv[u].x); wd[1] = f2tf(wv[u].y);
            wd[2] = f2tf(wv[u].z); wd[3] = f2tf(wv[u].w);
        }
        __syncthreads();

#pragma unroll
        for (int kc = 0; kc < 4; kc++) {
            const int kk = kc * 8 + tig;
            unsigned af[4][4];
#pragma unroll
            for (int mt = 0; mt < 4; mt++) {
                const int row = 64 * wm + 16 * mt + g;
                af[mt][0] = Xs[row][kk];
                af[mt][1] = Xs[row + 8][kk];
                af[mt][2] = Xs[row][kk + 4];
                af[mt][3] = Xs[row + 8][kk + 4];
            }
            unsigned bf[4][2];
#pragma unroll
            for (int nt = 0; nt < 4; nt++) {
                const int n = 32 * wn + 8 * nt + g;
                bf[nt][0] = Ws[n][kk];
                bf[nt][1] = Ws[n][kk + 4];
            }
#pragma unroll
            for (int mt = 0; mt < 4; mt++)
#pragma unroll
                for (int nt = 0; nt < 4; nt++)
                    mma_tf32(acc[mt][nt], af[mt], bf[nt]);
        }
    }

    // Epilogue: bias, q scale, scatter into [B, NH, S, HD]
#pragma unroll
    for (int mt = 0; mt < 4; mt++) {
        const int mrow0 = m0 + 64 * wm + 16 * mt + g;
#pragma unroll
        for (int nt = 0; nt < 4; nt++) {
            const int n = n0 + 32 * wn + 8 * nt + 2 * tig;
            const float2 bb = *reinterpret_cast<const float2*>(bias + n);
            const int head = n >> 6;
            const int d = n & 63;
#pragma unroll
            for (int hv = 0; hv < 2; hv++) {
                const int m = mrow0 + 8 * hv;
                const int b = m >> 10;
                const int s = m & 1023;
                float2 val;
                val.x = (acc[mt][nt][2 * hv]     + bb.x) * qscale;
                val.y = (acc[mt][nt][2 * hv + 1] + bb.y) * qscale;
                *reinterpret_cast<float2*>(
                    out + (((size_t)(b * NHH + head)) * SS + s) * HDD + d) = val;
            }
        }
    }
}

// ---------------------------------------------------------------------------
// Kernel 2: flash attention with tf32 mma.
// CTA: 128 q-rows x one (b,h). 8 warps, warp = 16 q-rows x 64-key tile.
// grid = (8, NH, B), block = 256, dynamic smem ~102 KB.
// ---------------------------------------------------------------------------
#define AP 68   // smem pitch (words) for 64-wide tiles; 68 mod 32 = 4

__global__ __launch_bounds__(256, 2) void attn_mma_kernel(
    const float* __restrict__ rel,    // [B, NH, S, S]
    const float* __restrict__ mask,   // [B, 1, 1, S]
    float* __restrict__ out)          // [B, S, H]
{
    extern __shared__ unsigned sm[];
    unsigned* q_s = sm;                      // [128][AP]
    unsigned* k_s = q_s + 128 * AP;          // [64][AP]
    unsigned* v_s = k_s + 64 * AP;           // [64][AP]
    unsigned* p_s = v_s + 64 * AP;           // [128][AP], per-warp 16-row slices

    const int b  = blockIdx.z;
    const int h  = blockIdx.y;
    const int q0 = blockIdx.x * 128;
    const int bh = b * NHH + h;

    const int tid  = threadIdx.x;
    const int lane = tid & 31;
    const int wid  = tid >> 5;
    const int g    = lane >> 2;
    const int tig  = lane & 3;
    const int qr   = 16 * wid;     // warp's q-row base within tile

    const float* qg = g_q + (size_t)bh * SS * HDD;
    const float* kg = g_k + (size_t)bh * SS * HDD;
    const float* vg = g_v + (size_t)bh * SS * HDD;

    // Load Q tile (128x64), tf32-rounded
#pragma unroll
    for (int u = 0; u < 8; u++) {
        const int lin = tid + 256 * u;
        const int row = lin >> 4;
        const int c4  = (lin & 15) * 4;
        float4 t = *reinterpret_cast<const float4*>(
            qg + (size_t)(q0 + row) * HDD + c4);
        uint4 w;
        w.x = f2tf(t.x); w.y = f2tf(t.y); w.z = f2tf(t.z); w.w = f2tf(t.w);
        *reinterpret_cast<uint4*>(q_s + row * AP + c4) = w;
    }

    float m0v = -1e30f, m1v = -1e30f, l0v = 0.0f, l1v = 0.0f;
    float o[8][4];
#pragma unroll
    for (int nt = 0; nt < 8; nt++)
#pragma unroll
        for (int r = 0; r < 4; r++) o[nt][r] = 0.0f;

    for (int k0 = 0; k0 < SS; k0 += 64) {
        // Prefetch rel bias + mask into registers (regs only; before syncs)
        float2 rl[8][2];
        float2 mk[8];
#pragma unroll
        for (int nt = 0; nt < 8; nt++) {
            const int col = k0 + 8 * nt + 2 * tig;
            mk[nt] = *reinterpret_cast<const float2*>(mask + b * SS + col);
            const size_t rb0 = ((size_t)bh * SS + (q0 + qr + g)) * SS + col;
            rl[nt][0] = *reinterpret_cast<const float2*>(rel + rb0);
            rl[nt][1] = *reinterpret_cast<const float2*>(rel + rb0 + 8 * (size_t)SS);
        }

        __syncthreads();   // previous iteration's k_s/v_s readers are done

        // Load K and V tiles (64x64 each), tf32-rounded
#pragma unroll
        for (int u = 0; u < 4; u++) {
            const int lin = tid + 256 * u;
            const int row = lin >> 4;
            const int c4  = (lin & 15) * 4;
            float4 kt = *reinterpret_cast<const float4*>(
                kg + (size_t)(k0 + row) * HDD + c4);
            float4 vt = *reinterpret_cast<const float4*>(
                vg + (size_t)(k0 + row) * HDD + c4);
            uint4 kw, vw;
            kw.x = f2tf(kt.x); kw.y = f2tf(kt.y);
            kw.z = f2tf(kt.z); kw.w = f2tf(kt.w);
            vw.x = f2tf(vt.x); vw.y = f2tf(vt.y);
            vw.z = f2tf(vt.z); vw.w = f2tf(vt.w);
            *reinterpret_cast<uint4*>(k_s + row * AP + c4) = kw;
            *reinterpret_cast<uint4*>(v_s + row * AP + c4) = vw;
        }
        __syncthreads();

        // Scores: S(16x64) = Q_w (16x64) * K^T
        float sc[8][4];
#pragma unroll
        for (int nt = 0; nt < 8; nt++)
#pragma unroll
            for (int r = 0; r < 4; r++) sc[nt][r] = 0.0f;

#pragma unroll
        for (int kc = 0; kc < 8; kc++) {
            const int d = kc * 8 + tig;
            unsigned af[4];
            af[0] = q_s[(qr + g) * AP + d];
            af[1] = q_s[(qr + g + 8) * AP + d];
            af[2] = q_s[(qr + g) * AP + d + 4];
            af[3] = q_s[(qr + g + 8) * AP + d + 4];
#pragma unroll
            for (int nt = 0; nt < 8; nt++) {
                unsigned bf[2];
                bf[0] = k_s[(8 * nt + g) * AP + d];
                bf[1] = k_s[(8 * nt + g) * AP + d + 4];
                mma_tf32(sc[nt], af, bf);
            }
        }

        // Add rel bias + mask
#pragma unroll
        for (int nt = 0; nt < 8; nt++) {
            sc[nt][0] += rl[nt][0].x + mk[nt].x;
            sc[nt][1] += rl[nt][0].y + mk[nt].y;
            sc[nt][2] += rl[nt][1].x + mk[nt].x;
            sc[nt][3] += rl[nt][1].y + mk[nt].y;
        }

        // Online softmax. Row (qr+g) lives in this quad's sc[*][0..1],
        // row (qr+g+8) in sc[*][2..3]. Quad reduce via shfl_xor 1,2.
        {
            float tm0 = sc[0][0], tm1 = sc[0][2];
#pragma unroll
            for (int nt = 0; nt < 8; nt++) {
                tm0 = fmaxf(tm0, fmaxf(sc[nt][0], sc[nt][1]));
                tm1 = fmaxf(tm1, fmaxf(sc[nt][2], sc[nt][3]));
            }
            tm0 = fmaxf(tm0, __shfl_xor_sync(0xffffffffu, tm0, 1));
            tm0 = fmaxf(tm0, __shfl_xor_sync(0xffffffffu, tm0, 2));
            tm1 = fmaxf(tm1, __shfl_xor_sync(0xffffffffu, tm1, 1));
            tm1 = fmaxf(tm1, __shfl_xor_sync(0xffffffffu, tm1, 2));

            const float mn0 = fmaxf(m0v, tm0);
            const float mn1 = fmaxf(m1v, tm1);
            const float c0 = __expf(m0v - mn0);
            const float c1 = __expf(m1v - mn1);
            float ls0 = 0.0f, ls1 = 0.0f;
#pragma unroll
            for (int nt = 0; nt < 8; nt++) {
                sc[nt][0] = __expf(sc[nt][0] - mn0);
                sc[nt][1] = __expf(sc[nt][1] - mn0);
                sc[nt][2] = __expf(sc[nt][2] - mn1);
                sc[nt][3] = __expf(sc[nt][3] - mn1);
                ls0 += sc[nt][0] + sc[nt][1];
                ls1 += sc[nt][2] + sc[nt][3];
            }
            ls0 += __shfl_xor_sync(0xffffffffu, ls0, 1);
            ls0 += __shfl_xor_sync(0xffffffffu, ls0, 2);
            ls1 += __shfl_xor_sync(0xffffffffu, ls1, 1);
            ls1 += __shfl_xor_sync(0xffffffffu, ls1, 2);

            l0v = l0v * c0 + ls0;
            l1v = l1v * c1 + ls1;
            m0v = mn0; m1v = mn1;
#pragma unroll
            for (int nt = 0; nt < 8; nt++) {
                o[nt][0] *= c0; o[nt][1] *= c0;
                o[nt][2] *= c1; o[nt][3] *= c1;
            }
        }

        // C-frag -> A-frag layout change via per-warp smem slice
        __syncwarp();
#pragma unroll
        for (int nt = 0; nt < 8; nt++) {
            const int col = 8 * nt + 2 * tig;
            p_s[(qr + g) * AP + col]     = f2tf(sc[nt][0]);
            p_s[(qr + g) * AP + col + 1] = f2tf(sc[nt][1]);
            p_s[(qr + g + 8) * AP + col]     = f2tf(sc[nt][2]);
            p_s[(qr + g + 8) * AP + col + 1] = f2tf(sc[nt][3]);
        }
        __syncwarp();

        // O(16x64) += P(16x64) * V(64x64)
#pragma unroll
        for (int kc = 0; kc < 8; kc++) {
            const int kk = kc * 8 + tig;
            unsigned af[4];
            af[0] = p_s[(qr + g) * AP + kk];
            af[1] = p_s[(qr + g + 8) * AP + kk];
            af[2] = p_s[(qr + g) * AP + kk + 4];
            af[3] = p_s[(qr + g + 8) * AP + kk + 4];
#pragma unroll
            for (int nt = 0; nt < 8; nt++) {
                unsigned bf[2];
                bf[0] = v_s[(8 * kc + tig) * AP + 8 * nt + g];
                bf[1] = v_s[(8 * kc + tig + 4) * AP + 8 * nt + g];
                mma_tf32(o[nt], af, bf);
            }
        }
    }

    // Epilogue: normalize, write ctx to [B, S, H]
    const float inv0 = 1.0f / l0v;
    const float inv1 = 1.0f / l1v;
    const int s0 = q0 + qr + g;
    float* orow0 = out + ((size_t)(b * SS + s0)) * HH + h * HDD;
    float* orow1 = out + ((size_t)(b * SS + s0 + 8)) * HH + h * HDD;
#pragma unroll
    for (int nt = 0; nt < 8; nt++) {
        const int col = 8 * nt + 2 * tig;
        float2 v0, v1;
        v0.x = o[nt][0] * inv0; v0.y = o[nt][1] * inv0;
        v1.x = o[nt][2] * inv1; v1.y = o[nt][3] * inv1;
        *reinterpret_cast<float2*>(orow0 + col) = v0;
        *reinterpret_cast<float2*>(orow1 + col) = v1;
    }
}

// ---------------------------------------------------------------------------
// Launch
// ---------------------------------------------------------------------------
extern "C" void kernel_launch(void* const* d_in, const int* in_sizes, int n_in,
                              void* d_out, int out_size)
{
    const float* hidden = (const float*)d_in[0];
    const float* mask   = (const float*)d_in[1];
    const float* rel    = (const float*)d_in[2];
    const float* Wq     = (const float*)d_in[3];
    const float* bq     = (const float*)d_in[4];
    const float* Wk     = (const float*)d_in[5];
    const float* bk     = (const float*)d_in[6];
    const float* Wv     = (const float*)d_in[7];
    const float* bv     = (const float*)d_in[8];
    float* out = (float*)d_out;

    const int attn_smem = (128 + 64 + 64 + 128) * AP * (int)sizeof(unsigned);
    cudaFuncSetAttribute(attn_mma_kernel,
                         cudaFuncAttributeMaxDynamicSharedMemorySize,
                         attn_smem);

    // QKV projection: grid (N/128, M/128, 3)
    qkv_mma_kernel<<<dim3(HH / 128, (BB * SS) / 128, 3), 256>>>(
        hidden, Wq, bq, Wk, bk, Wv, bv);

    // Attention: grid (S/128, NH, B)
    attn_mma_kernel<<<dim3(SS / 128, NHH, BB), 256, attn_smem>>>(
        rel, mask, out);
}

// round 6
// speedup vs baseline: 3.1631x; 1.0298x over previous
#include <cuda_runtime.h>
#include <math.h>
#include <stdint.h>

// Problem constants
#define BB   8
#define SS   1024
#define HH   512
#define NHH  8
#define HDD  64

// Scratch for q, k, v in [B, NH, S, HD] layout (16 MB each).
__device__ float g_q[BB * NHH * SS * HDD];
__device__ float g_k[BB * NHH * SS * HDD];
__device__ float g_v[BB * NHH * SS * HDD];

// ---------------------------------------------------------------------------
// tf32 / mma / ldmatrix helpers
// ---------------------------------------------------------------------------
__device__ __forceinline__ unsigned f2tf(float x) {
    unsigned r;
    asm("cvt.rna.tf32.f32 %0, %1;" : "=r"(r) : "f"(x));
    return r;
}

// D(16x8,f32) += A(16x8,tf32,row) * B(8x8,tf32,col)
__device__ __forceinline__ void mma_tf32(float* d, const unsigned* a,
                                         const unsigned* b) {
    asm volatile(
        "mma.sync.aligned.m16n8k8.row.col.f32.tf32.tf32.f32 "
        "{%0,%1,%2,%3}, {%4,%5,%6,%7}, {%8,%9}, {%0,%1,%2,%3};"
        : "+f"(d[0]), "+f"(d[1]), "+f"(d[2]), "+f"(d[3])
        : "r"(a[0]), "r"(a[1]), "r"(a[2]), "r"(a[3]), "r"(b[0]), "r"(b[1]));
}

__device__ __forceinline__ void ldsm_x4(unsigned& r0, unsigned& r1,
                                        unsigned& r2, unsigned& r3,
                                        uint32_t addr) {
    asm volatile(
        "ldmatrix.sync.aligned.m8n8.x4.shared.b16 {%0,%1,%2,%3}, [%4];"
        : "=r"(r0), "=r"(r1), "=r"(r2), "=r"(r3) : "r"(addr));
}

// ---------------------------------------------------------------------------
// Kernel 1: QKV projection with tf32 mma + ldmatrix.
// CTA tile 128x128, BK=32. 8 warps: warp tile 64(m) x 32(n).
// grid = (4, 64, 3), block = 256.
// ---------------------------------------------------------------------------
#define QP 36   // smem pitch (words); 36 mod 8 = 4 -> ldmatrix conflict-free

__global__ __launch_bounds__(256) void qkv_mma_kernel(
    const float* __restrict__ x,
    const float* __restrict__ Wq, const float* __restrict__ bq,
    const float* __restrict__ Wk, const float* __restrict__ bk,
    const float* __restrict__ Wv, const float* __restrict__ bv)
{
    __shared__ unsigned Xs[128][QP];
    __shared__ unsigned Ws[128][QP];

    const int z = blockIdx.z;
    const float* W    = (z == 0) ? Wq : (z == 1) ? Wk : Wv;
    const float* bias = (z == 0) ? bq : (z == 1) ? bk : bv;
    float*       out  = (z == 0) ? g_q : (z == 1) ? g_k : g_v;
    const float qscale = (z == 0) ? 0.125f : 1.0f;

    const int m0 = blockIdx.y * 128;
    const int n0 = blockIdx.x * 128;
    const int tid  = threadIdx.x;
    const int lane = tid & 31;
    const int wid  = tid >> 5;
    const int g    = lane >> 2;
    const int tig  = lane & 3;
    const int wm   = wid & 1;
    const int wn   = wid >> 1;

    const int lrow = tid >> 3;
    const int lcol = (tid & 7) * 4;

    // ldmatrix base addresses (bytes)
    const uint32_t xs_b = (uint32_t)__cvta_generic_to_shared(&Xs[0][0]);
    const uint32_t ws_b = (uint32_t)__cvta_generic_to_shared(&Ws[0][0]);
    // A-frag: 16 rows, two 16B chunks
    uint32_t a_base[4];
#pragma unroll
    for (int mt = 0; mt < 4; mt++)
        a_base[mt] = xs_b + (uint32_t)((64 * wm + 16 * mt + (lane & 15)) * QP) * 4
                          + (uint32_t)(lane >> 4) * 16;
    // B-frag pairs p: rows 32wn+16p.. , chunk by (lane>>3)&1
    uint32_t b_base[2];
#pragma unroll
    for (int p = 0; p < 2; p++)
        b_base[p] = ws_b + (uint32_t)((32 * wn + 16 * p + (lane & 7)
                          + (lane >> 4) * 8) * QP) * 4
                          + (uint32_t)((lane >> 3) & 1) * 16;

    float acc[4][4][4];
#pragma unroll
    for (int mt = 0; mt < 4; mt++)
#pragma unroll
        for (int nt = 0; nt < 4; nt++)
#pragma unroll
            for (int r = 0; r < 4; r++) acc[mt][nt][r] = 0.0f;

    for (int k0 = 0; k0 < HH; k0 += 32) {
        float4 xv[4], wv[4];
#pragma unroll
        for (int u = 0; u < 4; u++) {
            xv[u] = *reinterpret_cast<const float4*>(
                x + (size_t)(m0 + lrow + 32 * u) * HH + k0 + lcol);
            wv[u] = *reinterpret_cast<const float4*>(
                W + (size_t)(n0 + lrow + 32 * u) * HH + k0 + lcol);
        }
        __syncthreads();
#pragma unroll
        for (int u = 0; u < 4; u++) {
            unsigned* xd = &Xs[lrow + 32 * u][lcol];
            xd[0] = f2tf(xv[u].x); xd[1] = f2tf(xv[u].y);
            xd[2] = f2tf(xv[u].z); xd[3] = f2tf(xv[u].w);
            unsigned* wd = &Ws[lrow + 32 * u][lcol];
            wd[0] = f2tf(wv[u].x); wd[1] = f2tf(wv[u].y);
            wd[2] = f2tf(wv[u].z); wd[3] = f2tf(wv[u].w);
        }
        __syncthreads();

#pragma unroll
        for (int kc = 0; kc < 4; kc++) {
            const uint32_t koff = (uint32_t)kc * 32;
            unsigned af[4][4];
#pragma unroll
            for (int mt = 0; mt < 4; mt++)
                ldsm_x4(af[mt][0], af[mt][1], af[mt][2], af[mt][3],
                        a_base[mt] + koff);
            unsigned bf[2][4];
#pragma unroll
            for (int p = 0; p < 2; p++)
                ldsm_x4(bf[p][0], bf[p][1], bf[p][2], bf[p][3],
                        b_base[p] + koff);
#pragma unroll
            for (int mt = 0; mt < 4; mt++)
#pragma unroll
                for (int p = 0; p < 2; p++) {
                    mma_tf32(acc[mt][2 * p],     af[mt], &bf[p][0]);
                    mma_tf32(acc[mt][2 * p + 1], af[mt], &bf[p][2]);
                }
        }
    }

    // Epilogue: bias, q scale, scatter into [B, NH, S, HD]
#pragma unroll
    for (int mt = 0; mt < 4; mt++) {
        const int mrow0 = m0 + 64 * wm + 16 * mt + g;
#pragma unroll
        for (int nt = 0; nt < 4; nt++) {
            const int n = n0 + 32 * wn + 8 * nt + 2 * tig;
            const float2 bb = *reinterpret_cast<const float2*>(bias + n);
            const int head = n >> 6;
            const int d = n & 63;
#pragma unroll
            for (int hv = 0; hv < 2; hv++) {
                const int m = mrow0 + 8 * hv;
                const int b = m >> 10;
                const int s = m & 1023;
                float2 val;
                val.x = (acc[mt][nt][2 * hv]     + bb.x) * qscale;
                val.y = (acc[mt][nt][2 * hv + 1] + bb.y) * qscale;
                *reinterpret_cast<float2*>(
                    out + (((size_t)(b * NHH + head)) * SS + s) * HDD + d) = val;
            }
        }
    }
}

// ---------------------------------------------------------------------------
// Kernel 2: flash attention, tf32 mma + ldmatrix.
// CTA: 128 q-rows x one (b,h). 4 warps, warp = 32 q-rows (mt=2) x 64-key tile.
// grid = (8, NH, B), block = 128, dynamic smem ~102 KB (2 CTAs/SM).
// ---------------------------------------------------------------------------
#define AP 68   // pitch (words); 68 mod 8 = 4 -> ldmatrix conflict-free

__global__ __launch_bounds__(128, 2) void attn_mma_kernel(
    const float* __restrict__ rel,    // [B, NH, S, S]
    const float* __restrict__ mask,   // [B, 1, 1, S]
    float* __restrict__ out)          // [B, S, H]
{
    extern __shared__ unsigned sm[];
    unsigned* q_s = sm;                      // [128][AP]
    unsigned* k_s = q_s + 128 * AP;          // [64][AP]
    unsigned* v_s = k_s + 64 * AP;           // [64][AP]
    unsigned* p_s = v_s + 64 * AP;           // [128][AP], per-warp 32-row slices

    const int b  = blockIdx.z;
    const int h  = blockIdx.y;
    const int q0 = blockIdx.x * 128;
    const int bh = b * NHH + h;

    const int tid  = threadIdx.x;
    const int lane = tid & 31;
    const int wid  = tid >> 5;     // 0..3
    const int g    = lane >> 2;
    const int tig  = lane & 3;
    const int qr   = 32 * wid;     // warp's q-row base in tile

    const float* qg = g_q + (size_t)bh * SS * HDD;
    const float* kg = g_k + (size_t)bh * SS * HDD;
    const float* vg = g_v + (size_t)bh * SS * HDD;

    // ldmatrix base addresses (bytes)
    const uint32_t q_sb = (uint32_t)__cvta_generic_to_shared(q_s);
    const uint32_t k_sb = (uint32_t)__cvta_generic_to_shared(k_s);
    const uint32_t p_sb = (uint32_t)__cvta_generic_to_shared(p_s);

    uint32_t qa_base[2], pa_base[2];
#pragma unroll
    for (int mt = 0; mt < 2; mt++) {
        const uint32_t ro = (uint32_t)((qr + 16 * mt + (lane & 15)) * AP) * 4
                          + (uint32_t)(lane >> 4) * 16;
        qa_base[mt] = q_sb + ro;
        pa_base[mt] = p_sb + ro;
    }
    uint32_t kb_base[4];
#pragma unroll
    for (int p = 0; p < 4; p++)
        kb_base[p] = k_sb + (uint32_t)((16 * p + (lane & 7)
                           + (lane >> 4) * 8) * AP) * 4
                           + (uint32_t)((lane >> 3) & 1) * 16;

    // Load Q tile (128x64), tf32-rounded: 16 float4 per thread
#pragma unroll
    for (int u = 0; u < 16; u++) {
        const int lin = tid + 128 * u;
        const int row = lin >> 4;
        const int c4  = (lin & 15) * 4;
        float4 t = *reinterpret_cast<const float4*>(
            qg + (size_t)(q0 + row) * HDD + c4);
        uint4 w;
        w.x = f2tf(t.x); w.y = f2tf(t.y); w.z = f2tf(t.z); w.w = f2tf(t.w);
        *reinterpret_cast<uint4*>(q_s + row * AP + c4) = w;
    }

    float mst[2][2], lst[2][2];
    float o[2][8][4];
#pragma unroll
    for (int mt = 0; mt < 2; mt++) {
        mst[mt][0] = mst[mt][1] = -1e30f;
        lst[mt][0] = lst[mt][1] = 0.0f;
#pragma unroll
        for (int nt = 0; nt < 8; nt++)
#pragma unroll
            for (int r = 0; r < 4; r++) o[mt][nt][r] = 0.0f;
    }

    for (int k0 = 0; k0 < SS; k0 += 64) {
        // Init score accumulators with rel + mask (loads issue first; their
        // latency hides under K/V load/convert/store + barrier below).
        float sc[2][8][4];
        {
            float2 mk[8];
#pragma unroll
            for (int nt = 0; nt < 8; nt++)
                mk[nt] = *reinterpret_cast<const float2*>(
                    mask + b * SS + k0 + 8 * nt + 2 * tig);
#pragma unroll
            for (int mt = 0; mt < 2; mt++) {
                const size_t rb = ((size_t)bh * SS + (q0 + qr + 16 * mt + g)) * SS
                                + k0 + 2 * tig;
#pragma unroll
                for (int nt = 0; nt < 8; nt++) {
                    float2 rA = *reinterpret_cast<const float2*>(rel + rb + 8 * nt);
                    float2 rB = *reinterpret_cast<const float2*>(
                        rel + rb + 8 * (size_t)SS + 8 * nt);
                    sc[mt][nt][0] = rA.x + mk[nt].x;
                    sc[mt][nt][1] = rA.y + mk[nt].y;
                    sc[mt][nt][2] = rB.x + mk[nt].x;
                    sc[mt][nt][3] = rB.y + mk[nt].y;
                }
            }
        }

        __syncthreads();   // previous iteration's k_s/v_s readers are done

        // Load K and V tiles (64x64 each), tf32-rounded: 8 float4 pairs/thread
#pragma unroll
        for (int u = 0; u < 8; u++) {
            const int lin = tid + 128 * u;
            const int row = lin >> 4;
            const int c4  = (lin & 15) * 4;
            float4 kt = *reinterpret_cast<const float4*>(
                kg + (size_t)(k0 + row) * HDD + c4);
            float4 vt = *reinterpret_cast<const float4*>(
                vg + (size_t)(k0 + row) * HDD + c4);
            uint4 kw, vw;
            kw.x = f2tf(kt.x); kw.y = f2tf(kt.y);
            kw.z = f2tf(kt.z); kw.w = f2tf(kt.w);
            vw.x = f2tf(vt.x); vw.y = f2tf(vt.y);
            vw.z = f2tf(vt.z); vw.w = f2tf(vt.w);
            *reinterpret_cast<uint4*>(k_s + row * AP + c4) = kw;
            *reinterpret_cast<uint4*>(v_s + row * AP + c4) = vw;
        }
        __syncthreads();

        // Scores: S(32x64) += Q_w (32x64) * K^T
#pragma unroll
        for (int kc = 0; kc < 8; kc++) {
            const uint32_t koff = (uint32_t)kc * 32;
            unsigned af[2][4];
            ldsm_x4(af[0][0], af[0][1], af[0][2], af[0][3], qa_base[0] + koff);
            ldsm_x4(af[1][0], af[1][1], af[1][2], af[1][3], qa_base[1] + koff);
#pragma unroll
            for (int p = 0; p < 4; p++) {
                unsigned bf[4];
                ldsm_x4(bf[0], bf[1], bf[2], bf[3], kb_base[p] + koff);
                mma_tf32(sc[0][2 * p],     af[0], &bf[0]);
                mma_tf32(sc[0][2 * p + 1], af[0], &bf[2]);
                mma_tf32(sc[1][2 * p],     af[1], &bf[0]);
                mma_tf32(sc[1][2 * p + 1], af[1], &bf[2]);
            }
        }

        // Online softmax per mt (rows qr+16mt+g and +8; quad reduce)
#pragma unroll
        for (int mt = 0; mt < 2; mt++) {
            float tm0 = sc[mt][0][0], tm1 = sc[mt][0][2];
#pragma unroll
            for (int nt = 0; nt < 8; nt++) {
                tm0 = fmaxf(tm0, fmaxf(sc[mt][nt][0], sc[mt][nt][1]));
                tm1 = fmaxf(tm1, fmaxf(sc[mt][nt][2], sc[mt][nt][3]));
            }
            tm0 = fmaxf(tm0, __shfl_xor_sync(0xffffffffu, tm0, 1));
            tm0 = fmaxf(tm0, __shfl_xor_sync(0xffffffffu, tm0, 2));
            tm1 = fmaxf(tm1, __shfl_xor_sync(0xffffffffu, tm1, 1));
            tm1 = fmaxf(tm1, __shfl_xor_sync(0xffffffffu, tm1, 2));

            const float mn0 = fmaxf(mst[mt][0], tm0);
            const float mn1 = fmaxf(mst[mt][1], tm1);
            const float c0 = __expf(mst[mt][0] - mn0);
            const float c1 = __expf(mst[mt][1] - mn1);
            float ls0 = 0.0f, ls1 = 0.0f;
#pragma unroll
            for (int nt = 0; nt < 8; nt++) {
                sc[mt][nt][0] = __expf(sc[mt][nt][0] - mn0);
                sc[mt][nt][1] = __expf(sc[mt][nt][1] - mn0);
                sc[mt][nt][2] = __expf(sc[mt][nt][2] - mn1);
                sc[mt][nt][3] = __expf(sc[mt][nt][3] - mn1);
                ls0 += sc[mt][nt][0] + sc[mt][nt][1];
                ls1 += sc[mt][nt][2] + sc[mt][nt][3];
            }
            ls0 += __shfl_xor_sync(0xffffffffu, ls0, 1);
            ls0 += __shfl_xor_sync(0xffffffffu, ls0, 2);
            ls1 += __shfl_xor_sync(0xffffffffu, ls1, 1);
            ls1 += __shfl_xor_sync(0xffffffffu, ls1, 2);

            lst[mt][0] = lst[mt][0] * c0 + ls0;
            lst[mt][1] = lst[mt][1] * c1 + ls1;
            mst[mt][0] = mn0; mst[mt][1] = mn1;
#pragma unroll
            for (int nt = 0; nt < 8; nt++) {
                o[mt][nt][0] *= c0; o[mt][nt][1] *= c0;
                o[mt][nt][2] *= c1; o[mt][nt][3] *= c1;
            }
        }

        // C-frag -> A-frag via per-warp p_s slice (warp-local, syncwarp only)
        __syncwarp();
#pragma unroll
        for (int mt = 0; mt < 2; mt++) {
            const int r0w = qr + 16 * mt + g;
#pragma unroll
            for (int nt = 0; nt < 8; nt++) {
                const int col = 8 * nt + 2 * tig;
                uint2 lo, hi;
                lo.x = f2tf(sc[mt][nt][0]); lo.y = f2tf(sc[mt][nt][1]);
                hi.x = f2tf(sc[mt][nt][2]); hi.y = f2tf(sc[mt][nt][3]);
                *reinterpret_cast<uint2*>(p_s + r0w * AP + col) = lo;
                *reinterpret_cast<uint2*>(p_s + (r0w + 8) * AP + col) = hi;
            }
        }
        __syncwarp();

        // O(32x64) += P(32x64) * V(64x64)
#pragma unroll
        for (int kc = 0; kc < 8; kc++) {
            const uint32_t koff = (uint32_t)kc * 32;
            unsigned af[2][4];
            ldsm_x4(af[0][0], af[0][1], af[0][2], af[0][3], pa_base[0] + koff);
            ldsm_x4(af[1][0], af[1][1], af[1][2], af[1][3], pa_base[1] + koff);
#pragma unroll
            for (int nt = 0; nt < 8; nt++) {
                unsigned bf[2];
                bf[0] = v_s[(8 * kc + tig) * AP + 8 * nt + g];
                bf[1] = v_s[(8 * kc + tig + 4) * AP + 8 * nt + g];
                mma_tf32(o[0][nt], af[0], bf);
                mma_tf32(o[1][nt], af[1], bf);
            }
        }
    }

    // Epilogue: normalize, write ctx to [B, S, H]
#pragma unroll
    for (int mt = 0; mt < 2; mt++) {
        const float inv0 = 1.0f / lst[mt][0];
        const float inv1 = 1.0f / lst[mt][1];
        const int s0 = q0 + qr + 16 * mt + g;
        float* orow0 = out + ((size_t)(b * SS + s0)) * HH + h * HDD;
        float* orow1 = out + ((size_t)(b * SS + s0 + 8)) * HH + h * HDD;
#pragma unroll
        for (int nt = 0; nt < 8; nt++) {
            const int col = 8 * nt + 2 * tig;
            float2 v0, v1;
            v0.x = o[mt][nt][0] * inv0; v0.y = o[mt][nt][1] * inv0;
            v1.x = o[mt][nt][2] * inv1; v1.y = o[mt][nt][3] * inv1;
            *reinterpret_cast<float2*>(orow0 + col) = v0;
            *reinterpret_cast<float2*>(orow1 + col) = v1;
        }
    }
}

// ---------------------------------------------------------------------------
// Launch
// ---------------------------------------------------------------------------
extern "C" void kernel_launch(void* const* d_in, const int* in_sizes, int n_in,
                              void* d_out, int out_size)
{
    const float* hidden = (const float*)d_in[0];
    const float* mask   = (const float*)d_in[1];
    const float* rel    = (const float*)d_in[2];
    const float* Wq     = (const float*)d_in[3];
    const float* bq     = (const float*)d_in[4];
    const float* Wk     = (const float*)d_in[5];
    const float* bk     = (const float*)d_in[6];
    const float* Wv     = (const float*)d_in[7];
    const float* bv     = (const float*)d_in[8];
    float* out = (float*)d_out;

    const int attn_smem = (128 + 64 + 64 + 128) * AP * (int)sizeof(unsigned);
    cudaFuncSetAttribute(attn_mma_kernel,
                         cudaFuncAttributeMaxDynamicSharedMemorySize,
                         attn_smem);

    // QKV projection: grid (N/128, M/128, 3)
    qkv_mma_kernel<<<dim3(HH / 128, (BB * SS) / 128, 3), 256>>>(
        hidden, Wq, bq, Wk, bk, Wv, bv);

    // Attention: grid (S/128, NH, B)
    attn_mma_kernel<<<dim3(SS / 128, NHH, BB), 128, attn_smem>>>(
        rel, mask, out);
}